// round 1
// baseline (speedup 1.0000x reference)
#include <cuda_runtime.h>
#include <math.h>

#define N 8192
#define D 256
#define TI 16   // rows of output per block
#define TJ 32   // j-tile (columns of adj / rows of x) per shared-memory stage

// Scratch (device globals: no allocation allowed)
__device__ float g_h2[N];
__device__ float g_u[N];

// ---------------------------------------------------------------------------
// K1: h2[j] = input[j,:] . A[0:D]   (one warp per row)
// ---------------------------------------------------------------------------
__global__ void k_h2(const float* __restrict__ input, const float* __restrict__ A) {
    int warp = (blockIdx.x * blockDim.x + threadIdx.x) >> 5;
    int lane = threadIdx.x & 31;
    if (warp >= N) return;
    const float* row = input + warp * D;
    float v = 0.f;
#pragma unroll
    for (int t = 0; t < D / 32; t++) {
        int k = lane + t * 32;
        v += row[k] * A[k];   // A[:D] (h1 uses A[D:], but it cancels in softmax)
    }
#pragma unroll
    for (int o = 16; o; o >>= 1) v += __shfl_xor_sync(0xffffffffu, v, o);
    if (lane == 0) g_h2[warp] = v;
}

// ---------------------------------------------------------------------------
// K2: g = max_j h2[j];  u[j] = exp(h2[j] - g)    (single block)
// ---------------------------------------------------------------------------
__global__ void k_u() {
    __shared__ float smax[1024];
    int tid = threadIdx.x;
    float m = -INFINITY;
    for (int j = tid; j < N; j += 1024) m = fmaxf(m, g_h2[j]);
    smax[tid] = m;
    __syncthreads();
#pragma unroll
    for (int s = 512; s; s >>= 1) {
        if (tid < s) smax[tid] = fmaxf(smax[tid], smax[tid + s]);
        __syncthreads();
    }
    float g = smax[0];
    for (int j = tid; j < N; j += 1024) g_u[j] = expf(g_h2[j] - g);
}

// ---------------------------------------------------------------------------
// K3: out[i,:] = (sum_j adj[i,j]*u[j]*x[j,:]) / (sum_j adj[i,j]*u[j])
//
// Block: 256 threads, TI=16 output rows. Thread owns 4 rows x 4 cols (float4).
//   kq = tid % 64  -> float4 column index (k = 4*kq)
//   rg = tid / 64  -> row group (rows rg*4 .. rg*4+3)
// Per j: 1x LDS.128 (x) + 4x broadcast LDS (w) + 16 FFMA  => FMA-issue bound.
// ---------------------------------------------------------------------------
__global__ __launch_bounds__(256, 4) void k_main(const float* __restrict__ input,
                                                 const int* __restrict__ adj,
                                                 float* __restrict__ out) {
    __shared__ float xs[TJ * D];     // 32 KB
    __shared__ float ws[TI * TJ];    // 2 KB
    __shared__ float dsh[TI];

    int tid  = threadIdx.x;
    int row0 = blockIdx.x * TI;
    int kq = tid & 63;
    int rg = tid >> 6;

    float acc[4][4];
#pragma unroll
    for (int r = 0; r < 4; r++)
#pragma unroll
        for (int c = 0; c < 4; c++) acc[r][c] = 0.f;
    float denAcc = 0.f;

    for (int j0 = 0; j0 < N; j0 += TJ) {
        // Stage x tile: TJ*D floats = 2048 float4, 8 per thread (coalesced)
        const float4* in4 = (const float4*)(input + j0 * D);
        float4* xs4 = (float4*)xs;
#pragma unroll
        for (int t = 0; t < (TJ * D / 4) / 256; t++)
            xs4[tid + t * 256] = in4[tid + t * 256];

        // Stage weights: ws[i][jj] = adj ? u[j] : 0   (512 vals, 2 per thread)
#pragma unroll
        for (int t = 0; t < 2; t++) {
            int idx = tid + t * 256;
            int i  = idx >> 5;   // / TJ
            int jj = idx & 31;   // % TJ
            int a = adj[(row0 + i) * N + (j0 + jj)];
            ws[idx] = (a > 0) ? g_u[j0 + jj] : 0.f;
        }
        __syncthreads();

        // Per-row denominator (threads 0..15, one row each)
        if (tid < TI) {
#pragma unroll
            for (int jj = 0; jj < TJ; jj++) denAcc += ws[tid * TJ + jj];
        }

        // Main accumulate
#pragma unroll 4
        for (int jj = 0; jj < TJ; jj++) {
            float4 xv = ((const float4*)xs)[jj * 64 + kq];
#pragma unroll
            for (int r = 0; r < 4; r++) {
                float w = ws[(rg * 4 + r) * TJ + jj];
                acc[r][0] += w * xv.x;
                acc[r][1] += w * xv.y;
                acc[r][2] += w * xv.z;
                acc[r][3] += w * xv.w;
            }
        }
        __syncthreads();
    }

    if (tid < TI) dsh[tid] = denAcc;
    __syncthreads();

#pragma unroll
    for (int r = 0; r < 4; r++) {
        int row = row0 + rg * 4 + r;
        float inv = 1.0f / dsh[rg * 4 + r];
        float4 o;
        o.x = acc[r][0] * inv;
        o.y = acc[r][1] * inv;
        o.z = acc[r][2] * inv;
        o.w = acc[r][3] * inv;
        ((float4*)out)[row * (D / 4) + kq] = o;
    }
}

// ---------------------------------------------------------------------------
extern "C" void kernel_launch(void* const* d_in, const int* in_sizes, int n_in,
                              void* d_out, int out_size) {
    const float* input = (const float*)d_in[0];   // [N, D] f32
    const int*   adj   = (const int*)d_in[1];     // [N, N] i32
    const float* A     = (const float*)d_in[2];   // [2D, 1] f32
    float* out = (float*)d_out;                   // [N, D] f32

    k_h2<<<N / 8, 256>>>(input, A);   // 8 warps/block, one warp per row
    k_u<<<1, 1024>>>();
    k_main<<<N / TI, 256>>>(input, adj, out);
}

// round 3
// speedup vs baseline: 3.5576x; 3.5576x over previous
#include <cuda_runtime.h>
#include <cuda_bf16.h>
#include <math.h>
#include <stdint.h>

#define NN 8192
#define DF 256
#define KT 32                 // j per stage
#define KHALF (NN / 2)        // split-K = 2
#define NSTG (KHALF / KT)     // 128 stages
#define MROWS 128

// ---------------- device scratch ----------------
__device__ float g_h2[NN];
__device__ float g_u[NN];
__device__ __nv_bfloat16 g_Yhi[(size_t)DF * NN];   // Y^T hi [feature][j], j-perm per 32-block
__device__ __nv_bfloat16 g_Ylo[(size_t)DF * NN];   // Y^T lo
__device__ float g_num[2ull * NN * DF];
__device__ float g_den[2ull * NN];

// ---------------- smem layout ----------------
#define SM_A    0                     // 2 x 8192   (adj bf16, 128 rows x 64B)
#define SM_BHI  16384                 // 2 x 16896  (264 rows x 64B: 256 Y-hi + u + 7 zero)
#define SM_BLO  50176                 // 2 x 16384  (256 rows x 64B)
#define BHI_STRIDE 16896
#define SMEM_BYTES 82944

// j-permutation within a 32 block: element r -> 8*q + 2*slot + o
// (g = r/16, p = (r%16)/2, o = r&1, q = p&3, slot = (p>>2) + 2*g)
// Makes B fragments one LDS.128 and A fragment pairs one LDS.64.
__host__ __device__ __forceinline__ int permj(int r) {
    int g = r >> 4, p = (r & 15) >> 1, o = r & 1;
    int q = p & 3, slot = (p >> 2) + 2 * g;
    return 8 * q + 2 * slot + o;
}

__device__ __forceinline__ void mma_bf16(float* c, const uint32_t* a, uint32_t b0, uint32_t b1) {
    asm volatile(
        "mma.sync.aligned.m16n8k16.row.col.f32.bf16.bf16.f32 "
        "{%0,%1,%2,%3}, {%4,%5,%6,%7}, {%8,%9}, {%0,%1,%2,%3};"
        : "+f"(c[0]), "+f"(c[1]), "+f"(c[2]), "+f"(c[3])
        : "r"(a[0]), "r"(a[1]), "r"(a[2]), "r"(a[3]), "r"(b0), "r"(b1));
}

__device__ __forceinline__ uint32_t smem_u32(const void* p) {
    uint32_t a;
    asm("{ .reg .u64 t; cvta.to.shared.u64 t, %1; cvt.u32.u64 %0, t; }" : "=r"(a) : "l"(p));
    return a;
}

// ---------------------------------------------------------------------------
// Prep 1: h2[j] = input[j,:] . A[0:D]   (h1 term cancels in softmax)
// ---------------------------------------------------------------------------
__global__ void k_h2(const float* __restrict__ input, const float* __restrict__ A) {
    int warp = (blockIdx.x * blockDim.x + threadIdx.x) >> 5;
    int lane = threadIdx.x & 31;
    if (warp >= NN) return;
    const float* row = input + (size_t)warp * DF;
    float v = 0.f;
#pragma unroll
    for (int t = 0; t < DF / 32; t++) v += row[lane + t * 32] * A[lane + t * 32];
#pragma unroll
    for (int o = 16; o; o >>= 1) v += __shfl_xor_sync(0xffffffffu, v, o);
    if (lane == 0) g_h2[warp] = v;
}

// ---------------------------------------------------------------------------
// Prep 2: global max + u[j] = exp(h2[j]-g)   (row max cancels in the ratio)
// ---------------------------------------------------------------------------
__global__ void k_u() {
    __shared__ float smax[1024];
    int tid = threadIdx.x;
    float m = -INFINITY;
    for (int j = tid; j < NN; j += 1024) m = fmaxf(m, g_h2[j]);
    smax[tid] = m;
    __syncthreads();
#pragma unroll
    for (int s = 512; s; s >>= 1) {
        if (tid < s) smax[tid] = fmaxf(smax[tid], smax[tid + s]);
        __syncthreads();
    }
    float g = smax[0];
    for (int j = tid; j < NN; j += 1024) g_u[j] = expf(g_h2[j] - g);
}

// ---------------------------------------------------------------------------
// Prep 3: Y^T = (u*x)^T split hi/lo bf16, j-permuted within 32-blocks
// ---------------------------------------------------------------------------
__global__ void k_y(const float* __restrict__ input) {
    __shared__ float tile[32][33];
    int j0 = blockIdx.x * 32, k0 = blockIdx.y * 32;
    int tx = threadIdx.x, ty = threadIdx.y;
#pragma unroll
    for (int r = 0; r < 32; r += 8) {
        int j = j0 + ty + r;
        tile[ty + r][tx] = input[(size_t)j * DF + k0 + tx] * g_u[j];
    }
    __syncthreads();
#pragma unroll
    for (int r = 0; r < 32; r += 8) {
        int k = k0 + ty + r;
        float y = tile[tx][ty + r];
        __nv_bfloat16 hi = __float2bfloat16(y);
        float lo = y - __bfloat162float(hi);
        int jp = j0 + permj(tx);
        g_Yhi[(size_t)k * NN + jp] = hi;
        g_Ylo[(size_t)k * NN + jp] = __float2bfloat16(lo);
    }
}

// ---------------------------------------------------------------------------
// Main: num = adj @ (Yhi + Ylo); den = adj @ u  — mma.sync bf16, fp32 accum
// grid 128: ks = bid&1 (K split), row block = (bid>>1)*128
// ---------------------------------------------------------------------------
__global__ __launch_bounds__(256, 1) void k_main(const int* __restrict__ adj) {
    extern __shared__ char smem[];
    const uint32_t sb = smem_u32(smem);
    const int tid = threadIdx.x;
    const int wid = tid >> 5, lane = tid & 31;
    const int wm = wid & 1, wn = wid >> 1;         // 2 M-warps x 4 N-warps
    const int rA = lane >> 2, qA = lane & 3;
    const int ks = blockIdx.x & 1;
    const int row0 = (blockIdx.x >> 1) * MROWS;
    const int jb = ks * KHALF;

    // zero Bhi rows 257..263 (den-pad) in both buffers
    for (int w = tid; w < 224; w += 256) {
        int buf = w / 112, idx = w % 112;
        *(uint32_t*)(smem + SM_BHI + buf * BHI_STRIDE + 257 * 64 + idx * 4) = 0u;
    }

    float acc[4][8][4];
    float accd[4][4];
#pragma unroll
    for (int mf = 0; mf < 4; mf++) {
#pragma unroll
        for (int nf = 0; nf < 8; nf++)
#pragma unroll
            for (int c = 0; c < 4; c++) acc[mf][nf][c] = 0.f;
#pragma unroll
        for (int c = 0; c < 4; c++) accd[mf][c] = 0.f;
    }

    // A: thread covers 1 row (tid>>1), 16 j (tid&1 half), 4 int4
    const int ar = tid >> 1, ah = tid & 1;

    auto loadB = [&](int s) {
        int buf = s & 1;
        int j0 = jb + s * KT;
#pragma unroll
        for (int i = 0; i < 8; i++) {
            int id = i * 256 + tid;                 // 0..2047
            int half = id >> 10;                    // 0=hi 1=lo
            int row = (id >> 2) & 255;
            int ch = id & 3;
            const __nv_bfloat16* src =
                (half ? g_Ylo : g_Yhi) + (size_t)row * NN + j0 + ch * 8;
            uint32_t dst = sb + (half ? SM_BLO + buf * 16384 : SM_BHI + buf * BHI_STRIDE)
                         + row * 64 + ch * 16;
            asm volatile("cp.async.cg.shared.global [%0], [%1], 16;" :: "r"(dst), "l"(src));
        }
        if (tid < KT) {   // u row (B row 256) for denominator
            __nv_bfloat16 uv = __float2bfloat16(g_u[j0 + tid]);
            *(__nv_bfloat16*)(smem + SM_BHI + buf * BHI_STRIDE + 256 * 64 + 2 * permj(tid)) = uv;
        }
        asm volatile("cp.async.commit_group;" ::: "memory");
    };
    auto loadAdj = [&](int s, int4* r) {
        const int4* base = (const int4*)(adj + (size_t)(row0 + ar) * NN + jb + s * KT + ah * 16);
#pragma unroll
        for (int c = 0; c < 4; c++) r[c] = base[c];
    };
    auto storeA = [&](int s, const int4* r) {
        int buf = s & 1;
        char* arow = smem + SM_A + buf * 8192 + ar * 64;
#pragma unroll
        for (int c = 0; c < 4; c++) {
            uint32_t v0 = (r[c].x > 0 ? 0x3F80u : 0u) | (r[c].y > 0 ? 0x3F800000u : 0u);
            uint32_t v1 = (r[c].z > 0 ? 0x3F80u : 0u) | (r[c].w > 0 ? 0x3F800000u : 0u);
            int P0 = 8 * ah + 2 * c;                // even pair index
#pragma unroll
            for (int e = 0; e < 2; e++) {
                int P = P0 + e;
                int g = P >> 3, pp = P & 7;
                int byte = 16 * (pp & 3) + 4 * ((pp >> 2) + 2 * g);
                *(uint32_t*)(arow + byte) = e ? v1 : v0;
            }
        }
    };

    int4 regs[4];
    loadAdj(0, regs);
    storeA(0, regs);
    loadB(0);
    loadAdj(1, regs);

    for (int s = 0; s < NSTG; s++) {
        asm volatile("cp.async.wait_group 0;" ::: "memory");
        __syncthreads();
        if (s + 1 < NSTG) {
            loadB(s + 1);
            storeA(s + 1, regs);
        }
        if (s + 2 < NSTG) loadAdj(s + 2, regs);

        // ---- compute stage s ----
        int buf = s & 1;
        const char* As = smem + SM_A + buf * 8192;
        const char* Bh = smem + SM_BHI + buf * BHI_STRIDE;
        const char* Bl = smem + SM_BLO + buf * 16384;

        uint32_t af[4][2][4];
#pragma unroll
        for (int mf = 0; mf < 4; mf++)
#pragma unroll
            for (int g = 0; g < 2; g++) {
                int row = wm * 64 + mf * 16 + rA;
                uint2 lo = *(const uint2*)(As + row * 64 + 16 * qA + 8 * g);
                uint2 hi = *(const uint2*)(As + (row + 8) * 64 + 16 * qA + 8 * g);
                af[mf][g][0] = lo.x; af[mf][g][2] = lo.y;   // a0, a2
                af[mf][g][1] = hi.x; af[mf][g][3] = hi.y;   // a1, a3
            }

#pragma unroll
        for (int nf = 0; nf < 8; nf++) {
            int n = wn * 64 + nf * 8 + rA;
            uint4 bh = *(const uint4*)(Bh + n * 64 + 16 * qA);
#pragma unroll
            for (int mf = 0; mf < 4; mf++) {
                mma_bf16(acc[mf][nf], af[mf][0], bh.x, bh.y);
                mma_bf16(acc[mf][nf], af[mf][1], bh.z, bh.w);
            }
            uint4 bl = *(const uint4*)(Bl + n * 64 + 16 * qA);
#pragma unroll
            for (int mf = 0; mf < 4; mf++) {
                mma_bf16(acc[mf][nf], af[mf][0], bl.x, bl.y);
                mma_bf16(acc[mf][nf], af[mf][1], bl.z, bl.w);
            }
        }
        if (wn == 0) {   // denominator fragment: B rows 256..263 of hi tile
            uint4 bd = *(const uint4*)(Bh + (256 + rA) * 64 + 16 * qA);
#pragma unroll
            for (int mf = 0; mf < 4; mf++) {
                mma_bf16(accd[mf], af[mf][0], bd.x, bd.y);
                mma_bf16(accd[mf], af[mf][1], bd.z, bd.w);
            }
        }
        __syncthreads();
    }

    // ---- epilogue: store split-K partials ----
#pragma unroll
    for (int mf = 0; mf < 4; mf++) {
        int row = row0 + wm * 64 + mf * 16 + rA;
        int col = wn * 64 + qA * 2;
#pragma unroll
        for (int nf = 0; nf < 8; nf++) {
            float* p0 = g_num + ((size_t)ks * NN + row) * DF + col + nf * 8;
            float* p1 = g_num + ((size_t)ks * NN + row + 8) * DF + col + nf * 8;
            *(float2*)p0 = make_float2(acc[mf][nf][0], acc[mf][nf][1]);
            *(float2*)p1 = make_float2(acc[mf][nf][2], acc[mf][nf][3]);
        }
        if (wn == 0 && qA == 0) {
            g_den[(size_t)ks * NN + row] = accd[mf][0];
            g_den[(size_t)ks * NN + row + 8] = accd[mf][2];
        }
    }
}

// ---------------------------------------------------------------------------
// Combine split-K partials: out = (n0+n1)/(d0+d1)
// ---------------------------------------------------------------------------
__global__ void k_combine(float* __restrict__ out) {
    int id = blockIdx.x * 256 + threadIdx.x;
    int row = id >> 6, kq = id & 63;
    float4 a = ((const float4*)(g_num + (size_t)row * DF))[kq];
    float4 b = ((const float4*)(g_num + ((size_t)NN + row) * DF))[kq];
    float inv = 1.0f / (g_den[row] + g_den[NN + row]);
    float4 o;
    o.x = (a.x + b.x) * inv;
    o.y = (a.y + b.y) * inv;
    o.z = (a.z + b.z) * inv;
    o.w = (a.w + b.w) * inv;
    ((float4*)out)[id] = o;
}

// ---------------------------------------------------------------------------
extern "C" void kernel_launch(void* const* d_in, const int* in_sizes, int n_in,
                              void* d_out, int out_size) {
    const float* input = (const float*)d_in[0];
    const int*   adj   = (const int*)d_in[1];
    const float* A     = (const float*)d_in[2];
    float* out = (float*)d_out;

    cudaFuncSetAttribute(k_main, cudaFuncAttributeMaxDynamicSharedMemorySize, SMEM_BYTES);

    k_h2<<<NN / 8, 256>>>(input, A);
    k_u<<<1, 1024>>>();
    k_y<<<dim3(NN / 32, DF / 32), dim3(32, 8)>>>(input);
    k_main<<<128, 256, SMEM_BYTES>>>(adj);
    k_combine<<<(NN * DF / 4) / 256, 256>>>(out);
}

// round 4
// speedup vs baseline: 4.1305x; 1.1610x over previous
#include <cuda_runtime.h>
#include <cuda_bf16.h>
#include <math.h>
#include <stdint.h>

#define NN 8192
#define DF 256
#define KT 32                 // j per stage
#define KHALF (NN / 2)        // split-K = 2
#define NSTG (KHALF / KT)     // 128 stages
#define NBUF 3

// per-buffer smem layout
#define OFF_A   0             // 8KB : adj bf16, 128 rows x 64B
#define OFF_BH  8192          // 16KB: Yhi, 256 rows x 64B
#define OFF_BL  24576         // 16KB: Ylo
#define BUFSZ   40960
#define SMEM_BYTES (NBUF * BUFSZ)   // 122880

// ---------------- device scratch ----------------
__device__ float g_h2[NN];
__device__ float g_u[NN];
__device__ __nv_bfloat16 g_Yhi[(size_t)DF * NN];   // Y^T hi [feature][j], j-perm per 32-block
__device__ __nv_bfloat16 g_Ylo[(size_t)DF * NN];   // Y^T lo
__device__ float g_num[2ull * NN * DF];
__device__ float g_den[2ull * NN];

// j-permutation within a 32 block (verified in R3):
// makes B fragments one LDS.128 and A fragment pairs one LDS.64
__host__ __device__ __forceinline__ int permj(int r) {
    int g = r >> 4, p = (r & 15) >> 1, o = r & 1;
    int q = p & 3, slot = (p >> 2) + 2 * g;
    return 8 * q + 2 * slot + o;
}

__device__ __forceinline__ void mma_bf16(float* c, const uint32_t* a, uint32_t b0, uint32_t b1) {
    asm volatile(
        "mma.sync.aligned.m16n8k16.row.col.f32.bf16.bf16.f32 "
        "{%0,%1,%2,%3}, {%4,%5,%6,%7}, {%8,%9}, {%0,%1,%2,%3};"
        : "+f"(c[0]), "+f"(c[1]), "+f"(c[2]), "+f"(c[3])
        : "r"(a[0]), "r"(a[1]), "r"(a[2]), "r"(a[3]), "r"(b0), "r"(b1));
}

__device__ __forceinline__ uint32_t smem_u32(const void* p) {
    uint32_t a;
    asm("{ .reg .u64 t; cvta.to.shared.u64 t, %1; cvt.u32.u64 %0, t; }" : "=r"(a) : "l"(p));
    return a;
}

// ---------------------------------------------------------------------------
// Prep 1: h2[j] = input[j,:] . A[0:D]   (h1 term cancels in softmax)
// ---------------------------------------------------------------------------
__global__ void k_h2(const float* __restrict__ input, const float* __restrict__ A) {
    int warp = (blockIdx.x * blockDim.x + threadIdx.x) >> 5;
    int lane = threadIdx.x & 31;
    if (warp >= NN) return;
    const float* row = input + (size_t)warp * DF;
    float v = 0.f;
#pragma unroll
    for (int t = 0; t < DF / 32; t++) v += row[lane + t * 32] * A[lane + t * 32];
#pragma unroll
    for (int o = 16; o; o >>= 1) v += __shfl_xor_sync(0xffffffffu, v, o);
    if (lane == 0) g_h2[warp] = v;
}

// ---------------------------------------------------------------------------
// Prep 2: global max + u[j] = exp(h2[j]-g)   (row max cancels in the ratio)
// ---------------------------------------------------------------------------
__global__ void k_u() {
    __shared__ float smax[1024];
    int tid = threadIdx.x;
    float m = -INFINITY;
    for (int j = tid; j < NN; j += 1024) m = fmaxf(m, g_h2[j]);
    smax[tid] = m;
    __syncthreads();
#pragma unroll
    for (int s = 512; s; s >>= 1) {
        if (tid < s) smax[tid] = fmaxf(smax[tid], smax[tid + s]);
        __syncthreads();
    }
    float g = smax[0];
    for (int j = tid; j < NN; j += 1024) g_u[j] = expf(g_h2[j] - g);
}

// ---------------------------------------------------------------------------
// Prep 3: Y^T = (u*x)^T split hi/lo bf16, j-permuted within 32-blocks
// ---------------------------------------------------------------------------
__global__ void k_y(const float* __restrict__ input) {
    __shared__ float tile[32][33];
    int j0 = blockIdx.x * 32, k0 = blockIdx.y * 32;
    int tx = threadIdx.x, ty = threadIdx.y;
#pragma unroll
    for (int r = 0; r < 32; r += 8) {
        int j = j0 + ty + r;
        tile[ty + r][tx] = input[(size_t)j * DF + k0 + tx] * g_u[j];
    }
    __syncthreads();
#pragma unroll
    for (int r = 0; r < 32; r += 8) {
        int k = k0 + ty + r;
        float y = tile[tx][ty + r];
        __nv_bfloat16 hi = __float2bfloat16(y);
        float lo = y - __bfloat162float(hi);
        int jp = j0 + permj(tx);
        g_Yhi[(size_t)k * NN + jp] = hi;
        g_Ylo[(size_t)k * NN + jp] = __float2bfloat16(lo);
    }
}

// ---------------------------------------------------------------------------
// Main: num = adj @ (Yhi + Ylo)  via mma.sync bf16; den = adj.u in scalar FFMA
// grid 128: ks = bid&1 (K split), row block = (bid>>1)*128
// 512 threads, warps 2M x 8N, warp tile 64x32, 3-deep cp.async pipeline
// ---------------------------------------------------------------------------
__global__ __launch_bounds__(512, 1) void k_main(const int* __restrict__ adj) {
    extern __shared__ char smem[];
    const uint32_t sb = smem_u32(smem);
    const int tid = threadIdx.x;
    const int wid = tid >> 5, lane = tid & 31;
    const int wm = wid & 1, wn = wid >> 1;         // 2 M-warps x 8 N-warps
    const int rA = lane >> 2, qA = lane & 3;
    const int ks = blockIdx.x & 1;
    const int row0 = (blockIdx.x >> 1) * 128;
    const int jb = ks * KHALF;
    // A-operand staging: thread owns row ar, 8 j's (quarter aq)
    const int ar = tid >> 2, aq = tid & 3;

    float acc[4][4][4];
#pragma unroll
    for (int mf = 0; mf < 4; mf++)
#pragma unroll
        for (int nf = 0; nf < 4; nf++)
#pragma unroll
            for (int c = 0; c < 4; c++) acc[mf][nf][c] = 0.f;
    float den = 0.f;

    auto loadB = [&](int s) {
        uint32_t base = sb + (s % NBUF) * BUFSZ;
        int j0 = jb + s * KT;
#pragma unroll
        for (int i = 0; i < 4; i++) {
            int id = i * 512 + tid;                 // 0..2047
            int half = id >> 10;                    // 0=hi 1=lo
            int row = (id >> 2) & 255;
            int ch = id & 3;
            const __nv_bfloat16* src =
                (half ? g_Ylo : g_Yhi) + (size_t)row * NN + j0 + ch * 8;
            uint32_t dst = base + (half ? OFF_BL : OFF_BH) + row * 64 + ch * 16;
            asm volatile("cp.async.cg.shared.global [%0], [%1], 16;" :: "r"(dst), "l"(src));
        }
        asm volatile("cp.async.commit_group;" ::: "memory");
    };
    auto loadAdj = [&](int s, int4* r) {
        const int4* base = (const int4*)(adj + (size_t)(row0 + ar) * NN + jb + s * KT + aq * 8);
        r[0] = base[0];
        r[1] = base[1];
    };
    auto storeA = [&](int s, const int4* r) {
        char* arow = smem + (s % NBUF) * BUFSZ + OFF_A + ar * 64;
        const float4* up = (const float4*)(g_u + jb + s * KT + aq * 8);
        float4 u0 = up[0], u1 = up[1];
        // scalar denominator accumulation (replaces den MMA)
        den += (r[0].x > 0 ? u0.x : 0.f) + (r[0].y > 0 ? u0.y : 0.f)
             + (r[0].z > 0 ? u0.z : 0.f) + (r[0].w > 0 ? u0.w : 0.f)
             + (r[1].x > 0 ? u1.x : 0.f) + (r[1].y > 0 ? u1.y : 0.f)
             + (r[1].z > 0 ? u1.z : 0.f) + (r[1].w > 0 ? u1.w : 0.f);
#pragma unroll
        for (int c = 0; c < 2; c++) {
            uint32_t v0 = (r[c].x > 0 ? 0x3F80u : 0u) | (r[c].y > 0 ? 0x3F800000u : 0u);
            uint32_t v1 = (r[c].z > 0 ? 0x3F80u : 0u) | (r[c].w > 0 ? 0x3F800000u : 0u);
            int P0 = 4 * aq + 2 * c;
#pragma unroll
            for (int e = 0; e < 2; e++) {
                int P = P0 + e;
                int g = P >> 3, pp = P & 7;
                int byte = 16 * (pp & 3) + 4 * ((pp >> 2) + 2 * g);
                *(uint32_t*)(arow + byte) = e ? v1 : v0;
            }
        }
    };

    // ---- prologue: stages 0,1 staged; adj(2) prefetched into regs ----
    loadB(0);
    loadB(1);
    {
        int4 t[2];
        loadAdj(0, t); storeA(0, t);
        loadAdj(1, t); storeA(1, t);
    }
    int4 regs[2];
    loadAdj(2, regs);

#pragma unroll 1
    for (int s = 0; s < NSTG; s++) {
        asm volatile("cp.async.wait_group 1;" ::: "memory");   // B(s) arrived
        __syncthreads();                                       // storeA(s) visible
        if (s + 2 < NSTG) {
            loadB(s + 2);
            storeA(s + 2, regs);
        } else {
            asm volatile("cp.async.commit_group;" ::: "memory");
        }
        if (s + 3 < NSTG) loadAdj(s + 3, regs);

        // ---- compute stage s ----
        const char* As = smem + (s % NBUF) * BUFSZ + OFF_A;
        const char* Bh = smem + (s % NBUF) * BUFSZ + OFF_BH;
        const char* Bl = smem + (s % NBUF) * BUFSZ + OFF_BL;

        uint32_t af[4][2][4];
#pragma unroll
        for (int mf = 0; mf < 4; mf++)
#pragma unroll
            for (int g = 0; g < 2; g++) {
                int row = wm * 64 + mf * 16 + rA;
                uint2 lo = *(const uint2*)(As + row * 64 + 16 * qA + 8 * g);
                uint2 hi = *(const uint2*)(As + (row + 8) * 64 + 16 * qA + 8 * g);
                af[mf][g][0] = lo.x; af[mf][g][2] = lo.y;
                af[mf][g][1] = hi.x; af[mf][g][3] = hi.y;
            }

#pragma unroll
        for (int nf = 0; nf < 4; nf++) {
            int n = wn * 32 + nf * 8 + rA;
            uint4 bh = *(const uint4*)(Bh + n * 64 + 16 * qA);
#pragma unroll
            for (int mf = 0; mf < 4; mf++) {
                mma_bf16(acc[mf][nf], af[mf][0], bh.x, bh.y);
                mma_bf16(acc[mf][nf], af[mf][1], bh.z, bh.w);
            }
            uint4 bl = *(const uint4*)(Bl + n * 64 + 16 * qA);
#pragma unroll
            for (int mf = 0; mf < 4; mf++) {
                mma_bf16(acc[mf][nf], af[mf][0], bl.x, bl.y);
                mma_bf16(acc[mf][nf], af[mf][1], bl.z, bl.w);
            }
        }
    }

    // ---- epilogue: split-K partials ----
#pragma unroll
    for (int mf = 0; mf < 4; mf++) {
        int row = row0 + wm * 64 + mf * 16 + rA;
#pragma unroll
        for (int nf = 0; nf < 4; nf++) {
            int col = wn * 32 + nf * 8 + qA * 2;
            float* p0 = g_num + ((size_t)ks * NN + row) * DF + col;
            float* p1 = g_num + ((size_t)ks * NN + row + 8) * DF + col;
            *(float2*)p0 = make_float2(acc[mf][nf][0], acc[mf][nf][1]);
            *(float2*)p1 = make_float2(acc[mf][nf][2], acc[mf][nf][3]);
        }
    }
    // den: reduce across the 4 threads (aq) sharing row ar
    den += __shfl_xor_sync(0xffffffffu, den, 1);
    den += __shfl_xor_sync(0xffffffffu, den, 2);
    if ((lane & 3) == 0) g_den[(size_t)ks * NN + row0 + ar] = den;
}

// ---------------------------------------------------------------------------
// Combine split-K partials: out = (n0+n1)/(d0+d1)
// ---------------------------------------------------------------------------
__global__ void k_combine(float* __restrict__ out) {
    int id = blockIdx.x * 256 + threadIdx.x;
    int row = id >> 6, kq = id & 63;
    float4 a = ((const float4*)(g_num + (size_t)row * DF))[kq];
    float4 b = ((const float4*)(g_num + ((size_t)NN + row) * DF))[kq];
    float inv = 1.0f / (g_den[row] + g_den[NN + row]);
    float4 o;
    o.x = (a.x + b.x) * inv;
    o.y = (a.y + b.y) * inv;
    o.z = (a.z + b.z) * inv;
    o.w = (a.w + b.w) * inv;
    ((float4*)out)[id] = o;
}

// ---------------------------------------------------------------------------
extern "C" void kernel_launch(void* const* d_in, const int* in_sizes, int n_in,
                              void* d_out, int out_size) {
    const float* input = (const float*)d_in[0];
    const int*   adj   = (const int*)d_in[1];
    const float* A     = (const float*)d_in[2];
    float* out = (float*)d_out;

    cudaFuncSetAttribute(k_main, cudaFuncAttributeMaxDynamicSharedMemorySize, SMEM_BYTES);

    k_h2<<<NN / 8, 256>>>(input, A);
    k_u<<<1, 1024>>>();
    k_y<<<dim3(NN / 32, DF / 32), dim3(32, 8)>>>(input);
    k_main<<<128, 512, SMEM_BYTES>>>(adj);
    k_combine<<<(NN * DF / 4) / 256, 256>>>(out);
}

// round 5
// speedup vs baseline: 5.6591x; 1.3701x over previous
#include <cuda_runtime.h>
#include <cuda_fp16.h>
#include <math.h>
#include <stdint.h>

#define NN 8192
#define DF 256
#define KT 32                 // j per stage
#define KHALF (NN / 2)        // split-K = 2
#define NSTG (KHALF / KT)     // 128 stages
#define NBUF 4
#define YSCALE 2048.0f

// per-buffer smem layout
#define OFF_A   0             // 8KB : adj fp16, 128 rows x 64B
#define OFF_B   8192          // 16KB: Y fp16, 256 rows x 64B
#define BUFSZ   24576
#define SMEM_BYTES (NBUF * BUFSZ)   // 98304

// ---------------- device scratch ----------------
__device__ float g_h2[NN];
__device__ float g_u[NN];
__device__ __half g_Yh[(size_t)DF * NN];   // (u*x*2048)^T fp16 [feature][j], j-perm per 32-block
__device__ float g_num[2ull * NN * DF];
__device__ float g_den[2ull * NN];

// j-permutation within a 32 block (verified R3/R4):
// makes B fragments one LDS.128 and A fragment pairs one LDS.64
__host__ __device__ __forceinline__ int permj(int r) {
    int g = r >> 4, p = (r & 15) >> 1, o = r & 1;
    int q = p & 3, slot = (p >> 2) + 2 * g;
    return 8 * q + 2 * slot + o;
}

__device__ __forceinline__ void mma_fp16(float* c, const uint32_t* a, uint32_t b0, uint32_t b1) {
    asm volatile(
        "mma.sync.aligned.m16n8k16.row.col.f32.f16.f16.f32 "
        "{%0,%1,%2,%3}, {%4,%5,%6,%7}, {%8,%9}, {%0,%1,%2,%3};"
        : "+f"(c[0]), "+f"(c[1]), "+f"(c[2]), "+f"(c[3])
        : "r"(a[0]), "r"(a[1]), "r"(a[2]), "r"(a[3]), "r"(b0), "r"(b1));
}

__device__ __forceinline__ uint32_t smem_u32(const void* p) {
    uint32_t a;
    asm("{ .reg .u64 t; cvta.to.shared.u64 t, %1; cvt.u32.u64 %0, t; }" : "=r"(a) : "l"(p));
    return a;
}

// ---------------------------------------------------------------------------
// Prep 1: h2[j] = input[j,:] . A[0:D]   (h1 term cancels in softmax)
// ---------------------------------------------------------------------------
__global__ void k_h2(const float* __restrict__ input, const float* __restrict__ A) {
    int warp = (blockIdx.x * blockDim.x + threadIdx.x) >> 5;
    int lane = threadIdx.x & 31;
    if (warp >= NN) return;
    const float* row = input + (size_t)warp * DF;
    float v = 0.f;
#pragma unroll
    for (int t = 0; t < DF / 32; t++) v += row[lane + t * 32] * A[lane + t * 32];
#pragma unroll
    for (int o = 16; o; o >>= 1) v += __shfl_xor_sync(0xffffffffu, v, o);
    if (lane == 0) g_h2[warp] = v;
}

// ---------------------------------------------------------------------------
// Prep 2: global max + u[j] = exp(h2[j]-g)   (row max cancels in the ratio)
// ---------------------------------------------------------------------------
__global__ void k_u() {
    __shared__ float smax[1024];
    int tid = threadIdx.x;
    float m = -INFINITY;
    for (int j = tid; j < NN; j += 1024) m = fmaxf(m, g_h2[j]);
    smax[tid] = m;
    __syncthreads();
#pragma unroll
    for (int s = 512; s; s >>= 1) {
        if (tid < s) smax[tid] = fmaxf(smax[tid], smax[tid + s]);
        __syncthreads();
    }
    float g = smax[0];
    for (int j = tid; j < NN; j += 1024) g_u[j] = expf(g_h2[j] - g);
}

// ---------------------------------------------------------------------------
// Prep 3: Y^T = (u*x*2048)^T fp16, j-permuted within 32-blocks
// ---------------------------------------------------------------------------
__global__ void k_y(const float* __restrict__ input) {
    __shared__ float tile[32][33];
    int j0 = blockIdx.x * 32, k0 = blockIdx.y * 32;
    int tx = threadIdx.x, ty = threadIdx.y;
#pragma unroll
    for (int r = 0; r < 32; r += 8) {
        int j = j0 + ty + r;
        tile[ty + r][tx] = input[(size_t)j * DF + k0 + tx] * (g_u[j] * YSCALE);
    }
    __syncthreads();
#pragma unroll
    for (int r = 0; r < 32; r += 8) {
        int k = k0 + ty + r;
        g_Yh[(size_t)k * NN + j0 + permj(tx)] = __float2half(tile[tx][ty + r]);
    }
}

// ---------------------------------------------------------------------------
// Main: num = adj @ Y (fp16 mma.sync, fp32 acc); den = adj.u scalar FFMA
// grid 128: ks = bid&1 (K split), row block = (bid>>1)*128
// 512 threads, warps 2M x 8N, warp tile 64x32, 4-deep cp.async pipeline
// ---------------------------------------------------------------------------
__global__ __launch_bounds__(512, 1) void k_main(const int* __restrict__ adj) {
    extern __shared__ char smem[];
    const uint32_t sb = smem_u32(smem);
    const int tid = threadIdx.x;
    const int wid = tid >> 5, lane = tid & 31;
    const int wm = wid & 1, wn = wid >> 1;         // 2 M-warps x 8 N-warps
    const int rA = lane >> 2, qA = lane & 3;
    const int ks = blockIdx.x & 1;
    const int row0 = (blockIdx.x >> 1) * 128;
    const int jb = ks * KHALF;
    const int ar = tid >> 2, aq = tid & 3;         // A staging: row ar, quarter aq

    float acc[4][4][4];
#pragma unroll
    for (int mf = 0; mf < 4; mf++)
#pragma unroll
        for (int nf = 0; nf < 4; nf++)
#pragma unroll
            for (int c = 0; c < 4; c++) acc[mf][nf][c] = 0.f;
    float den = 0.f;

    auto loadB = [&](int s) {
        uint32_t base = sb + (s % NBUF) * BUFSZ;
        int j0 = jb + s * KT;
#pragma unroll
        for (int i = 0; i < 2; i++) {
            int id = i * 512 + tid;                 // 0..1023
            int row = id >> 2;
            int ch = id & 3;
            const __half* src = g_Yh + (size_t)row * NN + j0 + ch * 8;
            uint32_t dst = base + OFF_B + row * 64 + ch * 16;
            asm volatile("cp.async.cg.shared.global [%0], [%1], 16;" :: "r"(dst), "l"(src));
        }
        asm volatile("cp.async.commit_group;" ::: "memory");
    };
    auto loadAdj = [&](int s, int4* r) {
        const int4* base = (const int4*)(adj + (size_t)(row0 + ar) * NN + jb + s * KT + aq * 8);
        r[0] = base[0];
        r[1] = base[1];
    };
    auto storeA = [&](int s, const int4* r) {
        char* arow = smem + (s % NBUF) * BUFSZ + OFF_A + ar * 64;
        const float4* up = (const float4*)(g_u + jb + s * KT + aq * 8);
        float4 u0 = up[0], u1 = up[1];
        den += (r[0].x > 0 ? u0.x : 0.f) + (r[0].y > 0 ? u0.y : 0.f)
             + (r[0].z > 0 ? u0.z : 0.f) + (r[0].w > 0 ? u0.w : 0.f)
             + (r[1].x > 0 ? u1.x : 0.f) + (r[1].y > 0 ? u1.y : 0.f)
             + (r[1].z > 0 ? u1.z : 0.f) + (r[1].w > 0 ? u1.w : 0.f);
#pragma unroll
        for (int c = 0; c < 2; c++) {
            uint32_t v0 = (r[c].x > 0 ? 0x3C00u : 0u) | (r[c].y > 0 ? 0x3C000000u : 0u);
            uint32_t v1 = (r[c].z > 0 ? 0x3C00u : 0u) | (r[c].w > 0 ? 0x3C000000u : 0u);
            int P0 = 4 * aq + 2 * c;
#pragma unroll
            for (int e = 0; e < 2; e++) {
                int P = P0 + e;
                int g = P >> 3, pp = P & 7;
                int byte = 16 * (pp & 3) + 4 * ((pp >> 2) + 2 * g);
                *(uint32_t*)(arow + byte) = e ? v1 : v0;
            }
        }
    };

    // ---- prologue: stages 0..2 staged; adj(3) prefetched into regs ----
    loadB(0); loadB(1); loadB(2);
    {
        int4 t[2];
        loadAdj(0, t); storeA(0, t);
        loadAdj(1, t); storeA(1, t);
        loadAdj(2, t); storeA(2, t);
    }
    int4 regs[2];
    loadAdj(3, regs);

#pragma unroll 1
    for (int s = 0; s < NSTG; s++) {
        asm volatile("cp.async.wait_group 2;" ::: "memory");   // B(s) arrived
        __syncthreads();                                       // storeA(s) visible
        if (s + 3 < NSTG) {
            loadB(s + 3);
            storeA(s + 3, regs);
        } else {
            asm volatile("cp.async.commit_group;" ::: "memory");
        }
        if (s + 4 < NSTG) loadAdj(s + 4, regs);

        // ---- compute stage s ----
        const char* As = smem + (s % NBUF) * BUFSZ + OFF_A;
        const char* Bs = smem + (s % NBUF) * BUFSZ + OFF_B;

        uint32_t af[4][2][4];
#pragma unroll
        for (int mf = 0; mf < 4; mf++)
#pragma unroll
            for (int g = 0; g < 2; g++) {
                int row = wm * 64 + mf * 16 + rA;
                uint2 lo = *(const uint2*)(As + row * 64 + 16 * qA + 8 * g);
                uint2 hi = *(const uint2*)(As + (row + 8) * 64 + 16 * qA + 8 * g);
                af[mf][g][0] = lo.x; af[mf][g][2] = lo.y;
                af[mf][g][1] = hi.x; af[mf][g][3] = hi.y;
            }

#pragma unroll
        for (int nf = 0; nf < 4; nf++) {
            int n = wn * 32 + nf * 8 + rA;
            uint4 bh = *(const uint4*)(Bs + n * 64 + 16 * qA);
#pragma unroll
            for (int mf = 0; mf < 4; mf++) {
                mma_fp16(acc[mf][nf], af[mf][0], bh.x, bh.y);
                mma_fp16(acc[mf][nf], af[mf][1], bh.z, bh.w);
            }
        }
    }

    // ---- epilogue: split-K partials ----
#pragma unroll
    for (int mf = 0; mf < 4; mf++) {
        int row = row0 + wm * 64 + mf * 16 + rA;
#pragma unroll
        for (int nf = 0; nf < 4; nf++) {
            int col = wn * 32 + nf * 8 + qA * 2;
            float* p0 = g_num + ((size_t)ks * NN + row) * DF + col;
            float* p1 = g_num + ((size_t)ks * NN + row + 8) * DF + col;
            *(float2*)p0 = make_float2(acc[mf][nf][0], acc[mf][nf][1]);
            *(float2*)p1 = make_float2(acc[mf][nf][2], acc[mf][nf][3]);
        }
    }
    den += __shfl_xor_sync(0xffffffffu, den, 1);
    den += __shfl_xor_sync(0xffffffffu, den, 2);
    if ((lane & 3) == 0) g_den[(size_t)ks * NN + row0 + ar] = den;
}

// ---------------------------------------------------------------------------
// Combine split-K partials: out = (n0+n1) / (YSCALE*(d0+d1))
// ---------------------------------------------------------------------------
__global__ void k_combine(float* __restrict__ out) {
    int id = blockIdx.x * 256 + threadIdx.x;
    int row = id >> 6, kq = id & 63;
    float4 a = ((const float4*)(g_num + (size_t)row * DF))[kq];
    float4 b = ((const float4*)(g_num + ((size_t)NN + row) * DF))[kq];
    float inv = 1.0f / (YSCALE * (g_den[row] + g_den[NN + row]));
    float4 o;
    o.x = (a.x + b.x) * inv;
    o.y = (a.y + b.y) * inv;
    o.z = (a.z + b.z) * inv;
    o.w = (a.w + b.w) * inv;
    ((float4*)out)[id] = o;
}

// ---------------------------------------------------------------------------
extern "C" void kernel_launch(void* const* d_in, const int* in_sizes, int n_in,
                              void* d_out, int out_size) {
    const float* input = (const float*)d_in[0];
    const int*   adj   = (const int*)d_in[1];
    const float* A     = (const float*)d_in[2];
    float* out = (float*)d_out;

    cudaFuncSetAttribute(k_main, cudaFuncAttributeMaxDynamicSharedMemorySize, SMEM_BYTES);

    k_h2<<<NN / 8, 256>>>(input, A);
    k_u<<<1, 1024>>>();
    k_y<<<dim3(NN / 32, DF / 32), dim3(32, 8)>>>(input);
    k_main<<<128, 512, SMEM_BYTES>>>(adj);
    k_combine<<<(NN * DF / 4) / 256, 256>>>(out);
}

// round 6
// speedup vs baseline: 6.1532x; 1.0873x over previous
#include <cuda_runtime.h>
#include <cuda_fp16.h>
#include <math.h>
#include <stdint.h>

#define NN 8192
#define DF 256
#define KT 32                 // j per stage
#define KHALF (NN / 2)        // split-K = 2
#define NSTG (KHALF / KT)     // 128 stages
#define NBUF 4
#define YSCALE 2048.0f
#define MROWS 64              // CTA M tile (2 CTAs/SM)

// per-buffer smem layout
#define OFF_A   0             // 4KB : adj fp16, 64 rows x 64B
#define OFF_B   4096          // 16KB: Y fp16, 256 rows x 64B
#define BUFSZ   20480
#define SMEM_BYTES (NBUF * BUFSZ)   // 81920

// ---------------- device scratch ----------------
__device__ float g_h2[NN];
__device__ float g_u[NN];
__device__ __half g_Yh[(size_t)DF * NN];   // (u*x*2048)^T fp16 [feature][j], j-perm per 32-block
__device__ float g_num[2ull * NN * DF];
__device__ float g_den[2ull * NN];

// j-permutation within a 32 block (verified R3-R5):
// makes B fragments one LDS.128 and A fragment pairs one LDS.64
__host__ __device__ __forceinline__ int permj(int r) {
    int g = r >> 4, p = (r & 15) >> 1, o = r & 1;
    int q = p & 3, slot = (p >> 2) + 2 * g;
    return 8 * q + 2 * slot + o;
}

__device__ __forceinline__ void mma_fp16(float* c, const uint32_t* a, uint32_t b0, uint32_t b1) {
    asm volatile(
        "mma.sync.aligned.m16n8k16.row.col.f32.f16.f16.f32 "
        "{%0,%1,%2,%3}, {%4,%5,%6,%7}, {%8,%9}, {%0,%1,%2,%3};"
        : "+f"(c[0]), "+f"(c[1]), "+f"(c[2]), "+f"(c[3])
        : "r"(a[0]), "r"(a[1]), "r"(a[2]), "r"(a[3]), "r"(b0), "r"(b1));
}

__device__ __forceinline__ uint32_t smem_u32(const void* p) {
    uint32_t a;
    asm("{ .reg .u64 t; cvta.to.shared.u64 t, %1; cvt.u32.u64 %0, t; }" : "=r"(a) : "l"(p));
    return a;
}

// ---------------------------------------------------------------------------
// Prep 1: h2[j] = input[j,:] . A[0:D]   (h1 term cancels in softmax)
// ---------------------------------------------------------------------------
__global__ void k_h2(const float* __restrict__ input, const float* __restrict__ A) {
    int warp = (blockIdx.x * blockDim.x + threadIdx.x) >> 5;
    int lane = threadIdx.x & 31;
    if (warp >= NN) return;
    const float* row = input + (size_t)warp * DF;
    float v = 0.f;
#pragma unroll
    for (int t = 0; t < DF / 32; t++) v += row[lane + t * 32] * A[lane + t * 32];
#pragma unroll
    for (int o = 16; o; o >>= 1) v += __shfl_xor_sync(0xffffffffu, v, o);
    if (lane == 0) g_h2[warp] = v;
}

// ---------------------------------------------------------------------------
// Prep 2: global max + u[j] = exp(h2[j]-g)   (row max cancels in the ratio)
// ---------------------------------------------------------------------------
__global__ void k_u() {
    __shared__ float smax[1024];
    int tid = threadIdx.x;
    float m = -INFINITY;
    for (int j = tid; j < NN; j += 1024) m = fmaxf(m, g_h2[j]);
    smax[tid] = m;
    __syncthreads();
#pragma unroll
    for (int s = 512; s; s >>= 1) {
        if (tid < s) smax[tid] = fmaxf(smax[tid], smax[tid + s]);
        __syncthreads();
    }
    float g = smax[0];
    for (int j = tid; j < NN; j += 1024) g_u[j] = expf(g_h2[j] - g);
}

// ---------------------------------------------------------------------------
// Prep 3: Y^T = (u*x*2048)^T fp16, j-permuted within 32-blocks
// ---------------------------------------------------------------------------
__global__ void k_y(const float* __restrict__ input) {
    __shared__ float tile[32][33];
    int j0 = blockIdx.x * 32, k0 = blockIdx.y * 32;
    int tx = threadIdx.x, ty = threadIdx.y;
#pragma unroll
    for (int r = 0; r < 32; r += 8) {
        int j = j0 + ty + r;
        tile[ty + r][tx] = input[(size_t)j * DF + k0 + tx] * (g_u[j] * YSCALE);
    }
    __syncthreads();
#pragma unroll
    for (int r = 0; r < 32; r += 8) {
        int k = k0 + ty + r;
        g_Yh[(size_t)k * NN + j0 + permj(tx)] = __float2half(tile[tx][ty + r]);
    }
}

// ---------------------------------------------------------------------------
// Main: num = adj @ Y (fp16 mma.sync, fp32 acc); den = adj.u scalar FFMA
// grid 256: ks = bid&1 (K split), row block = (bid>>1)*64
// 256 threads (8 warps, 1M x 8N, warp tile 64x32), 2 CTAs/SM, 4-deep pipeline
// ---------------------------------------------------------------------------
__global__ __launch_bounds__(256, 2) void k_main(const int* __restrict__ adj) {
    extern __shared__ char smem[];
    const uint32_t sb = smem_u32(smem);
    const int tid = threadIdx.x;
    const int wid = tid >> 5, lane = tid & 31;
    const int wn = wid;                            // 8 N-warps, warp tile 64x32
    const int rA = lane >> 2, qA = lane & 3;
    const int ks = blockIdx.x & 1;
    const int row0 = (blockIdx.x >> 1) * MROWS;
    const int jb = ks * KHALF;
    const int ar = tid >> 2, aq = tid & 3;         // A staging: row ar (0..63), quarter aq

    float acc[4][4][4];
#pragma unroll
    for (int mf = 0; mf < 4; mf++)
#pragma unroll
        for (int nf = 0; nf < 4; nf++)
#pragma unroll
            for (int c = 0; c < 4; c++) acc[mf][nf][c] = 0.f;
    float den = 0.f;

    auto loadB = [&](int s) {
        uint32_t base = sb + (s % NBUF) * BUFSZ;
        int j0 = jb + s * KT;
#pragma unroll
        for (int i = 0; i < 4; i++) {
            int id = i * 256 + tid;                 // 0..1023
            int row = id >> 2;
            int ch = id & 3;
            const __half* src = g_Yh + (size_t)row * NN + j0 + ch * 8;
            uint32_t dst = base + OFF_B + row * 64 + ch * 16;
            asm volatile("cp.async.cg.shared.global [%0], [%1], 16;" :: "r"(dst), "l"(src));
        }
        asm volatile("cp.async.commit_group;" ::: "memory");
    };
    auto loadAdj = [&](int s, int4* r) {
        const int4* base = (const int4*)(adj + (size_t)(row0 + ar) * NN + jb + s * KT + aq * 8);
        r[0] = base[0];
        r[1] = base[1];
    };
    auto storeA = [&](int s, const int4* r) {
        char* arow = smem + (s % NBUF) * BUFSZ + OFF_A + ar * 64;
        const float4* up = (const float4*)(g_u + jb + s * KT + aq * 8);
        float4 u0 = up[0], u1 = up[1];
        den += (r[0].x > 0 ? u0.x : 0.f) + (r[0].y > 0 ? u0.y : 0.f)
             + (r[0].z > 0 ? u0.z : 0.f) + (r[0].w > 0 ? u0.w : 0.f)
             + (r[1].x > 0 ? u1.x : 0.f) + (r[1].y > 0 ? u1.y : 0.f)
             + (r[1].z > 0 ? u1.z : 0.f) + (r[1].w > 0 ? u1.w : 0.f);
#pragma unroll
        for (int c = 0; c < 2; c++) {
            uint32_t v0 = (r[c].x > 0 ? 0x3C00u : 0u) | (r[c].y > 0 ? 0x3C000000u : 0u);
            uint32_t v1 = (r[c].z > 0 ? 0x3C00u : 0u) | (r[c].w > 0 ? 0x3C000000u : 0u);
            int P0 = 4 * aq + 2 * c;
#pragma unroll
            for (int e = 0; e < 2; e++) {
                int P = P0 + e;
                int g = P >> 3, pp = P & 7;
                int byte = 16 * (pp & 3) + 4 * ((pp >> 2) + 2 * g);
                *(uint32_t*)(arow + byte) = e ? v1 : v0;
            }
        }
    };

    // ---- prologue: stages 0..2 staged; adj(3) prefetched into regs ----
    loadB(0); loadB(1); loadB(2);
    {
        int4 t[2];
        loadAdj(0, t); storeA(0, t);
        loadAdj(1, t); storeA(1, t);
        loadAdj(2, t); storeA(2, t);
    }
    int4 regs[2];
    loadAdj(3, regs);

#pragma unroll 1
    for (int s = 0; s < NSTG; s++) {
        asm volatile("cp.async.wait_group 2;" ::: "memory");   // B(s) arrived
        __syncthreads();                                       // storeA(s) visible
        if (s + 3 < NSTG) {
            loadB(s + 3);
            storeA(s + 3, regs);
        } else {
            asm volatile("cp.async.commit_group;" ::: "memory");
        }
        if (s + 4 < NSTG) loadAdj(s + 4, regs);

        // ---- compute stage s ----
        const char* As = smem + (s % NBUF) * BUFSZ + OFF_A;
        const char* Bs = smem + (s % NBUF) * BUFSZ + OFF_B;

        uint32_t af[4][2][4];
#pragma unroll
        for (int mf = 0; mf < 4; mf++)
#pragma unroll
            for (int g = 0; g < 2; g++) {
                int row = mf * 16 + rA;
                uint2 lo = *(const uint2*)(As + row * 64 + 16 * qA + 8 * g);
                uint2 hi = *(const uint2*)(As + (row + 8) * 64 + 16 * qA + 8 * g);
                af[mf][g][0] = lo.x; af[mf][g][2] = lo.y;
                af[mf][g][1] = hi.x; af[mf][g][3] = hi.y;
            }

#pragma unroll
        for (int nf = 0; nf < 4; nf++) {
            int n = wn * 32 + nf * 8 + rA;
            uint4 bh = *(const uint4*)(Bs + n * 64 + 16 * qA);
#pragma unroll
            for (int mf = 0; mf < 4; mf++) {
                mma_fp16(acc[mf][nf], af[mf][0], bh.x, bh.y);
                mma_fp16(acc[mf][nf], af[mf][1], bh.z, bh.w);
            }
        }
    }

    // ---- epilogue: split-K partials ----
#pragma unroll
    for (int mf = 0; mf < 4; mf++) {
        int row = row0 + mf * 16 + rA;
#pragma unroll
        for (int nf = 0; nf < 4; nf++) {
            int col = wn * 32 + nf * 8 + qA * 2;
            float* p0 = g_num + ((size_t)ks * NN + row) * DF + col;
            float* p1 = g_num + ((size_t)ks * NN + row + 8) * DF + col;
            *(float2*)p0 = make_float2(acc[mf][nf][0], acc[mf][nf][1]);
            *(float2*)p1 = make_float2(acc[mf][nf][2], acc[mf][nf][3]);
        }
    }
    den += __shfl_xor_sync(0xffffffffu, den, 1);
    den += __shfl_xor_sync(0xffffffffu, den, 2);
    if ((lane & 3) == 0) g_den[(size_t)ks * NN + row0 + ar] = den;
}

// ---------------------------------------------------------------------------
// Combine split-K partials: out = (n0+n1) / (YSCALE*(d0+d1))
// ---------------------------------------------------------------------------
__global__ void k_combine(float* __restrict__ out) {
    int id = blockIdx.x * 256 + threadIdx.x;
    int row = id >> 6, kq = id & 63;
    float4 a = ((const float4*)(g_num + (size_t)row * DF))[kq];
    float4 b = ((const float4*)(g_num + ((size_t)NN + row) * DF))[kq];
    float inv = 1.0f / (YSCALE * (g_den[row] + g_den[NN + row]));
    float4 o;
    o.x = (a.x + b.x) * inv;
    o.y = (a.y + b.y) * inv;
    o.z = (a.z + b.z) * inv;
    o.w = (a.w + b.w) * inv;
    ((float4*)out)[id] = o;
}

// ---------------------------------------------------------------------------
extern "C" void kernel_launch(void* const* d_in, const int* in_sizes, int n_in,
                              void* d_out, int out_size) {
    const float* input = (const float*)d_in[0];
    const int*   adj   = (const int*)d_in[1];
    const float* A     = (const float*)d_in[2];
    float* out = (float*)d_out;

    cudaFuncSetAttribute(k_main, cudaFuncAttributeMaxDynamicSharedMemorySize, SMEM_BYTES);

    k_h2<<<NN / 8, 256>>>(input, A);
    k_u<<<1, 1024>>>();
    k_y<<<dim3(NN / 32, DF / 32), dim3(32, 8)>>>(input);
    k_main<<<256, 256, SMEM_BYTES>>>(adj);
    k_combine<<<(NN * DF / 4) / 256, 256>>>(out);
}

// round 7
// speedup vs baseline: 6.3511x; 1.0322x over previous
#include <cuda_runtime.h>
#include <cuda_fp16.h>
#include <math.h>
#include <stdint.h>

#define NN 8192
#define DF 256
#define KT 32                 // j per stage
#define KHALF (NN / 2)        // split-K = 2
#define NSTG (KHALF / KT)     // 128 stages
#define NBUF 4
#define YSCALE 2048.0f
#define MROWS 64              // CTA M tile (2 CTAs/SM)

// per-buffer smem layout
#define OFF_A   0             // 4KB : adj fp16, 64 rows x 64B
#define OFF_B   4096          // 16KB: Y fp16, 256 rows x 64B
#define BUFSZ   20480
#define SMEM_BYTES (NBUF * BUFSZ)   // 81920

// ---------------- device scratch ----------------
__device__ float g_h2[NN];
__device__ float g_u[NN];
__device__ __half g_Yh[(size_t)DF * NN];   // (u*x*2048)^T fp16 [feature][j], j-perm per 32-block
__device__ float g_num[2ull * NN * DF];
__device__ float g_den[2ull * NN];

// j-permutation within a 32 block (verified R3-R6):
// makes B fragments one LDS.128 and A fragment pairs one LDS.64
__host__ __device__ __forceinline__ int permj(int r) {
    int g = r >> 4, p = (r & 15) >> 1, o = r & 1;
    int q = p & 3, slot = (p >> 2) + 2 * g;
    return 8 * q + 2 * slot + o;
}

// NOTE: no volatile, no memory clobber — pure register op, let ptxas schedule
__device__ __forceinline__ void mma_fp16(float* c, const uint32_t* a, uint32_t b0, uint32_t b1) {
    asm("mma.sync.aligned.m16n8k16.row.col.f32.f16.f16.f32 "
        "{%0,%1,%2,%3}, {%4,%5,%6,%7}, {%8,%9}, {%0,%1,%2,%3};"
        : "+f"(c[0]), "+f"(c[1]), "+f"(c[2]), "+f"(c[3])
        : "r"(a[0]), "r"(a[1]), "r"(a[2]), "r"(a[3]), "r"(b0), "r"(b1));
}

__device__ __forceinline__ uint32_t smem_u32(const void* p) {
    uint32_t a;
    asm("{ .reg .u64 t; cvta.to.shared.u64 t, %1; cvt.u32.u64 %0, t; }" : "=r"(a) : "l"(p));
    return a;
}

// ---------------------------------------------------------------------------
// Prep 1: h2[j] = input[j,:] . A[0:D]   (h1 term cancels in softmax)
// ---------------------------------------------------------------------------
__global__ void k_h2(const float* __restrict__ input, const float* __restrict__ A) {
    int warp = (blockIdx.x * blockDim.x + threadIdx.x) >> 5;
    int lane = threadIdx.x & 31;
    if (warp >= NN) return;
    const float* row = input + (size_t)warp * DF;
    float v = 0.f;
#pragma unroll
    for (int t = 0; t < DF / 32; t++) v += row[lane + t * 32] * A[lane + t * 32];
#pragma unroll
    for (int o = 16; o; o >>= 1) v += __shfl_xor_sync(0xffffffffu, v, o);
    if (lane == 0) g_h2[warp] = v;
}

// ---------------------------------------------------------------------------
// Prep 2: global max + u[j] = exp(h2[j]-g)   (row max cancels in the ratio)
// ---------------------------------------------------------------------------
__global__ void k_u() {
    __shared__ float smax[1024];
    int tid = threadIdx.x;
    float m = -INFINITY;
    for (int j = tid; j < NN; j += 1024) m = fmaxf(m, g_h2[j]);
    smax[tid] = m;
    __syncthreads();
#pragma unroll
    for (int s = 512; s; s >>= 1) {
        if (tid < s) smax[tid] = fmaxf(smax[tid], smax[tid + s]);
        __syncthreads();
    }
    float g = smax[0];
    for (int j = tid; j < NN; j += 1024) g_u[j] = expf(g_h2[j] - g);
}

// ---------------------------------------------------------------------------
// Prep 3: Y^T = (u*x*2048)^T fp16, j-permuted within 32-blocks
// ---------------------------------------------------------------------------
__global__ void k_y(const float* __restrict__ input) {
    __shared__ float tile[32][33];
    int j0 = blockIdx.x * 32, k0 = blockIdx.y * 32;
    int tx = threadIdx.x, ty = threadIdx.y;
#pragma unroll
    for (int r = 0; r < 32; r += 8) {
        int j = j0 + ty + r;
        tile[ty + r][tx] = input[(size_t)j * DF + k0 + tx] * (g_u[j] * YSCALE);
    }
    __syncthreads();
#pragma unroll
    for (int r = 0; r < 32; r += 8) {
        int k = k0 + ty + r;
        g_Yh[(size_t)k * NN + j0 + permj(tx)] = __float2half(tile[tx][ty + r]);
    }
}

// ---------------------------------------------------------------------------
// Main: num = adj @ Y (fp16 mma.sync, fp32 acc); den = adj.u scalar FFMA
// grid 256: ks = bid&1 (K split), row block = (bid>>1)*64
// 256 threads (8 warps, 1M x 8N, warp tile 64x32), 2 CTAs/SM, 4-deep pipeline
// Inner loop: half-batched B + g-major MMA order -> RAW distance 8
// ---------------------------------------------------------------------------
__global__ __launch_bounds__(256, 2) void k_main(const int* __restrict__ adj) {
    extern __shared__ char smem[];
    const uint32_t sb = smem_u32(smem);
    const int tid = threadIdx.x;
    const int wid = tid >> 5, lane = tid & 31;
    const int wn = wid;                            // 8 N-warps, warp tile 64x32
    const int rA = lane >> 2, qA = lane & 3;
    const int ks = blockIdx.x & 1;
    const int row0 = (blockIdx.x >> 1) * MROWS;
    const int jb = ks * KHALF;
    const int ar = tid >> 2, aq = tid & 3;         // A staging: row ar (0..63), quarter aq

    float acc[4][4][4];
#pragma unroll
    for (int mf = 0; mf < 4; mf++)
#pragma unroll
        for (int nf = 0; nf < 4; nf++)
#pragma unroll
            for (int c = 0; c < 4; c++) acc[mf][nf][c] = 0.f;
    float den = 0.f;

    auto loadB = [&](int s) {
        uint32_t base = sb + (s % NBUF) * BUFSZ;
        int j0 = jb + s * KT;
#pragma unroll
        for (int i = 0; i < 4; i++) {
            int id = i * 256 + tid;                 // 0..1023
            int row = id >> 2;
            int ch = id & 3;
            const __half* src = g_Yh + (size_t)row * NN + j0 + ch * 8;
            uint32_t dst = base + OFF_B + row * 64 + ch * 16;
            asm volatile("cp.async.cg.shared.global [%0], [%1], 16;" :: "r"(dst), "l"(src));
        }
        asm volatile("cp.async.commit_group;" ::: "memory");
    };
    auto loadAdj = [&](int s, int4* r) {
        const int4* base = (const int4*)(adj + (size_t)(row0 + ar) * NN + jb + s * KT + aq * 8);
        r[0] = base[0];
        r[1] = base[1];
    };
    auto storeA = [&](int s, const int4* r) {
        char* arow = smem + (s % NBUF) * BUFSZ + OFF_A + ar * 64;
        const float4* up = (const float4*)(g_u + jb + s * KT + aq * 8);
        float4 u0 = up[0], u1 = up[1];
        den += (r[0].x > 0 ? u0.x : 0.f) + (r[0].y > 0 ? u0.y : 0.f)
             + (r[0].z > 0 ? u0.z : 0.f) + (r[0].w > 0 ? u0.w : 0.f)
             + (r[1].x > 0 ? u1.x : 0.f) + (r[1].y > 0 ? u1.y : 0.f)
             + (r[1].z > 0 ? u1.z : 0.f) + (r[1].w > 0 ? u1.w : 0.f);
#pragma unroll
        for (int c = 0; c < 2; c++) {
            uint32_t v0 = (r[c].x > 0 ? 0x3C00u : 0u) | (r[c].y > 0 ? 0x3C000000u : 0u);
            uint32_t v1 = (r[c].z > 0 ? 0x3C00u : 0u) | (r[c].w > 0 ? 0x3C000000u : 0u);
            int P0 = 4 * aq + 2 * c;
#pragma unroll
            for (int e = 0; e < 2; e++) {
                int P = P0 + e;
                int g = P >> 3, pp = P & 7;
                int byte = 16 * (pp & 3) + 4 * ((pp >> 2) + 2 * g);
                *(uint32_t*)(arow + byte) = e ? v1 : v0;
            }
        }
    };

    // ---- prologue: stages 0..2 staged; adj(3) prefetched into regs ----
    loadB(0); loadB(1); loadB(2);
    {
        int4 t[2];
        loadAdj(0, t); storeA(0, t);
        loadAdj(1, t); storeA(1, t);
        loadAdj(2, t); storeA(2, t);
    }
    int4 regs[2];
    loadAdj(3, regs);

#pragma unroll 1
    for (int s = 0; s < NSTG; s++) {
        asm volatile("cp.async.wait_group 2;" ::: "memory");   // B(s) arrived
        __syncthreads();                                       // storeA(s) visible
        if (s + 3 < NSTG) {
            loadB(s + 3);
            storeA(s + 3, regs);
        } else {
            asm volatile("cp.async.commit_group;" ::: "memory");
        }
        if (s + 4 < NSTG) loadAdj(s + 4, regs);

        // ---- compute stage s ----
        const char* As = smem + (s % NBUF) * BUFSZ + OFF_A;
        const char* Bs = smem + (s % NBUF) * BUFSZ + OFF_B;

        // prefetch all A fragments first
        uint32_t af[4][2][4];
#pragma unroll
        for (int mf = 0; mf < 4; mf++)
#pragma unroll
            for (int g = 0; g < 2; g++) {
                int row = mf * 16 + rA;
                uint2 lo = *(const uint2*)(As + row * 64 + 16 * qA + 8 * g);
                uint2 hi = *(const uint2*)(As + (row + 8) * 64 + 16 * qA + 8 * g);
                af[mf][g][0] = lo.x; af[mf][g][2] = lo.y;
                af[mf][g][1] = hi.x; af[mf][g][3] = hi.y;
            }

        // half-batched: two B fragments live, g-major MMA order (RAW distance 8)
#pragma unroll
        for (int h = 0; h < 2; h++) {
            int n0 = wn * 32 + (2 * h) * 8 + rA;
            int n1 = n0 + 8;
            uint4 b0 = *(const uint4*)(Bs + n0 * 64 + 16 * qA);
            uint4 b1 = *(const uint4*)(Bs + n1 * 64 + 16 * qA);
            // g = 0
#pragma unroll
            for (int mf = 0; mf < 4; mf++) mma_fp16(acc[mf][2 * h],     af[mf][0], b0.x, b0.y);
#pragma unroll
            for (int mf = 0; mf < 4; mf++) mma_fp16(acc[mf][2 * h + 1], af[mf][0], b1.x, b1.y);
            // g = 1
#pragma unroll
            for (int mf = 0; mf < 4; mf++) mma_fp16(acc[mf][2 * h],     af[mf][1], b0.z, b0.w);
#pragma unroll
            for (int mf = 0; mf < 4; mf++) mma_fp16(acc[mf][2 * h + 1], af[mf][1], b1.z, b1.w);
        }
    }

    // ---- epilogue: split-K partials ----
#pragma unroll
    for (int mf = 0; mf < 4; mf++) {
        int row = row0 + mf * 16 + rA;
#pragma unroll
        for (int nf = 0; nf < 4; nf++) {
            int col = wn * 32 + nf * 8 + qA * 2;
            float* p0 = g_num + ((size_t)ks * NN + row) * DF + col;
            float* p1 = g_num + ((size_t)ks * NN + row + 8) * DF + col;
            *(float2*)p0 = make_float2(acc[mf][nf][0], acc[mf][nf][1]);
            *(float2*)p1 = make_float2(acc[mf][nf][2], acc[mf][nf][3]);
        }
    }
    den += __shfl_xor_sync(0xffffffffu, den, 1);
    den += __shfl_xor_sync(0xffffffffu, den, 2);
    if ((lane & 3) == 0) g_den[(size_t)ks * NN + row0 + ar] = den;
}

// ---------------------------------------------------------------------------
// Combine split-K partials: out = (n0+n1) / (YSCALE*(d0+d1))
// ---------------------------------------------------------------------------
__global__ void k_combine(float* __restrict__ out) {
    int id = blockIdx.x * 256 + threadIdx.x;
    int row = id >> 6, kq = id & 63;
    float4 a = ((const float4*)(g_num + (size_t)row * DF))[kq];
    float4 b = ((const float4*)(g_num + ((size_t)NN + row) * DF))[kq];
    float inv = 1.0f / (YSCALE * (g_den[row] + g_den[NN + row]));
    float4 o;
    o.x = (a.x + b.x) * inv;
    o.y = (a.y + b.y) * inv;
    o.z = (a.z + b.z) * inv;
    o.w = (a.w + b.w) * inv;
    ((float4*)out)[id] = o;
}

// ---------------------------------------------------------------------------
extern "C" void kernel_launch(void* const* d_in, const int* in_sizes, int n_in,
                              void* d_out, int out_size) {
    const float* input = (const float*)d_in[0];
    const int*   adj   = (const int*)d_in[1];
    const float* A     = (const float*)d_in[2];
    float* out = (float*)d_out;

    cudaFuncSetAttribute(k_main, cudaFuncAttributeMaxDynamicSharedMemorySize, SMEM_BYTES);

    k_h2<<<NN / 8, 256>>>(input, A);
    k_u<<<1, 1024>>>();
    k_y<<<dim3(NN / 32, DF / 32), dim3(32, 8)>>>(input);
    k_main<<<256, 256, SMEM_BYTES>>>(adj);
    k_combine<<<(NN * DF / 4) / 256, 256>>>(out);
}

// round 8
// speedup vs baseline: 7.6296x; 1.2013x over previous
#include <cuda_runtime.h>
#include <cuda_fp16.h>
#include <math.h>
#include <stdint.h>

#define NN 8192
#define DF 256
#define KT 64                 // j per stage (two 32-j sub-stages)
#define KHALF (NN / 2)        // split-K = 2
#define NSTG (KHALF / KT)     // 64 stages
#define NBUF 2
#define YSCALE 2048.0f
#define MROWS 64              // CTA M tile (2 CTAs/SM)

// per-buffer smem layout: A sub-buffers (2 x 4KB) then B sub-buffers (2 x 16KB)
#define OFF_A0  0
#define OFF_A1  4096
#define OFF_B0  8192
#define OFF_B1  24576
#define BUFSZ   40960
#define SMEM_BYTES (NBUF * BUFSZ)   // 81920

// ---------------- device scratch ----------------
__device__ float g_h2[NN];
__device__ float g_u[NN];
__device__ __half g_Yh[(size_t)DF * NN];   // (u*x*2048)^T fp16 [feature][j], j-perm per 32-block
__device__ float g_num[2ull * NN * DF];
__device__ float g_den[2ull * NN];

// j-permutation within a 32 block (verified R3-R7):
// makes B fragments one LDS.128 and A fragment pairs one LDS.64
__host__ __device__ __forceinline__ int permj(int r) {
    int g = r >> 4, p = (r & 15) >> 1, o = r & 1;
    int q = p & 3, slot = (p >> 2) + 2 * g;
    return 8 * q + 2 * slot + o;
}

// no volatile / no memory clobber — pure register op, ptxas schedules freely
__device__ __forceinline__ void mma_fp16(float* c, const uint32_t* a, uint32_t b0, uint32_t b1) {
    asm("mma.sync.aligned.m16n8k16.row.col.f32.f16.f16.f32 "
        "{%0,%1,%2,%3}, {%4,%5,%6,%7}, {%8,%9}, {%0,%1,%2,%3};"
        : "+f"(c[0]), "+f"(c[1]), "+f"(c[2]), "+f"(c[3])
        : "r"(a[0]), "r"(a[1]), "r"(a[2]), "r"(a[3]), "r"(b0), "r"(b1));
}

__device__ __forceinline__ uint32_t smem_u32(const void* p) {
    uint32_t a;
    asm("{ .reg .u64 t; cvta.to.shared.u64 t, %1; cvt.u32.u64 %0, t; }" : "=r"(a) : "l"(p));
    return a;
}

// ---------------------------------------------------------------------------
// Prep 1: h2[j] = input[j,:] . A[0:D]   (h1 term cancels in softmax)
// ---------------------------------------------------------------------------
__global__ void k_h2(const float* __restrict__ input, const float* __restrict__ A) {
    int warp = (blockIdx.x * blockDim.x + threadIdx.x) >> 5;
    int lane = threadIdx.x & 31;
    if (warp >= NN) return;
    const float* row = input + (size_t)warp * DF;
    float v = 0.f;
#pragma unroll
    for (int t = 0; t < DF / 32; t++) v += row[lane + t * 32] * A[lane + t * 32];
#pragma unroll
    for (int o = 16; o; o >>= 1) v += __shfl_xor_sync(0xffffffffu, v, o);
    if (lane == 0) g_h2[warp] = v;
}

// ---------------------------------------------------------------------------
// Prep 2: global max + u[j] = exp(h2[j]-g)   (row max cancels in the ratio)
// ---------------------------------------------------------------------------
__global__ void k_u() {
    __shared__ float smax[1024];
    int tid = threadIdx.x;
    float m = -INFINITY;
    for (int j = tid; j < NN; j += 1024) m = fmaxf(m, g_h2[j]);
    smax[tid] = m;
    __syncthreads();
#pragma unroll
    for (int s = 512; s; s >>= 1) {
        if (tid < s) smax[tid] = fmaxf(smax[tid], smax[tid + s]);
        __syncthreads();
    }
    float g = smax[0];
    for (int j = tid; j < NN; j += 1024) g_u[j] = expf(g_h2[j] - g);
}

// ---------------------------------------------------------------------------
// Prep 3: Y^T = (u*x*2048)^T fp16, j-permuted within 32-blocks
// ---------------------------------------------------------------------------
__global__ void k_y(const float* __restrict__ input) {
    __shared__ float tile[32][33];
    int j0 = blockIdx.x * 32, k0 = blockIdx.y * 32;
    int tx = threadIdx.x, ty = threadIdx.y;
#pragma unroll
    for (int r = 0; r < 32; r += 8) {
        int j = j0 + ty + r;
        tile[ty + r][tx] = input[(size_t)j * DF + k0 + tx] * (g_u[j] * YSCALE);
    }
    __syncthreads();
#pragma unroll
    for (int r = 0; r < 32; r += 8) {
        int k = k0 + ty + r;
        g_Yh[(size_t)k * NN + j0 + permj(tx)] = __float2half(tile[tx][ty + r]);
    }
}

// ---------------------------------------------------------------------------
// Main: num = adj @ Y (fp16 mma.sync, fp32 acc); den = adj.u scalar FFMA
// grid 256: ks = bid&1 (K split), row block = (bid>>1)*64
// 256 threads (8 warps, 1M x 8N, warp tile 64x32), 2 CTAs/SM
// KT=64 stage = two KT-32 sub-stages; one barrier round per 32 MMAs/warp
// ---------------------------------------------------------------------------
__global__ __launch_bounds__(256, 2) void k_main(const int* __restrict__ adj) {
    extern __shared__ char smem[];
    const uint32_t sb = smem_u32(smem);
    const int tid = threadIdx.x;
    const int wid = tid >> 5, lane = tid & 31;
    const int wn = wid;                            // 8 N-warps, warp tile 64x32
    const int rA = lane >> 2, qA = lane & 3;
    const int ks = blockIdx.x & 1;
    const int row0 = (blockIdx.x >> 1) * MROWS;
    const int jb = ks * KHALF;
    const int ar = tid >> 2, aq = tid & 3;         // A staging: row ar (0..63), quarter aq

    float acc[4][4][4];
#pragma unroll
    for (int mf = 0; mf < 4; mf++)
#pragma unroll
        for (int nf = 0; nf < 4; nf++)
#pragma unroll
            for (int c = 0; c < 4; c++) acc[mf][nf][c] = 0.f;
    float den = 0.f;

    auto loadB = [&](int s) {
        uint32_t base = sb + (s & 1) * BUFSZ;
        int j0 = jb + s * KT;
#pragma unroll
        for (int kh = 0; kh < 2; kh++) {
#pragma unroll
            for (int i = 0; i < 4; i++) {
                int id = i * 256 + tid;             // 0..1023
                int row = id >> 2;
                int ch = id & 3;
                const __half* src = g_Yh + (size_t)row * NN + j0 + kh * 32 + ch * 8;
                uint32_t dst = base + (kh ? OFF_B1 : OFF_B0) + row * 64 + ch * 16;
                asm volatile("cp.async.cg.shared.global [%0], [%1], 16;" :: "r"(dst), "l"(src));
            }
        }
        asm volatile("cp.async.commit_group;" ::: "memory");
    };
    auto loadAdjH = [&](int s, int kh, int4* r) {
        const int4* base =
            (const int4*)(adj + (size_t)(row0 + ar) * NN + jb + s * KT + kh * 32 + aq * 8);
        r[0] = base[0];
        r[1] = base[1];
    };
    auto storeAH = [&](int s, int kh, const int4* r) {
        char* arow = smem + (s & 1) * BUFSZ + (kh ? OFF_A1 : OFF_A0) + ar * 64;
        const float4* up = (const float4*)(g_u + jb + s * KT + kh * 32 + aq * 8);
        float4 u0 = up[0], u1 = up[1];
        den += (r[0].x > 0 ? u0.x : 0.f) + (r[0].y > 0 ? u0.y : 0.f)
             + (r[0].z > 0 ? u0.z : 0.f) + (r[0].w > 0 ? u0.w : 0.f)
             + (r[1].x > 0 ? u1.x : 0.f) + (r[1].y > 0 ? u1.y : 0.f)
             + (r[1].z > 0 ? u1.z : 0.f) + (r[1].w > 0 ? u1.w : 0.f);
#pragma unroll
        for (int c = 0; c < 2; c++) {
            uint32_t v0 = (r[c].x > 0 ? 0x3C00u : 0u) | (r[c].y > 0 ? 0x3C000000u : 0u);
            uint32_t v1 = (r[c].z > 0 ? 0x3C00u : 0u) | (r[c].w > 0 ? 0x3C000000u : 0u);
            int P0 = 4 * aq + 2 * c;
#pragma unroll
            for (int e = 0; e < 2; e++) {
                int P = P0 + e;
                int g = P >> 3, pp = P & 7;
                int byte = 16 * (pp & 3) + 4 * ((pp >> 2) + 2 * g);
                *(uint32_t*)(arow + byte) = e ? v1 : v0;
            }
        }
    };
    auto computeKH = [&](const char* base, int kh) {
        const char* As = base + (kh ? OFF_A1 : OFF_A0);
        const char* Bs = base + (kh ? OFF_B1 : OFF_B0);
        uint32_t af[4][2][4];
#pragma unroll
        for (int mf = 0; mf < 4; mf++)
#pragma unroll
            for (int g = 0; g < 2; g++) {
                int row = mf * 16 + rA;
                uint2 lo = *(const uint2*)(As + row * 64 + 16 * qA + 8 * g);
                uint2 hi = *(const uint2*)(As + (row + 8) * 64 + 16 * qA + 8 * g);
                af[mf][g][0] = lo.x; af[mf][g][2] = lo.y;
                af[mf][g][1] = hi.x; af[mf][g][3] = hi.y;
            }
#pragma unroll
        for (int h = 0; h < 2; h++) {
            int n0 = wn * 32 + (2 * h) * 8 + rA;
            uint4 b0 = *(const uint4*)(Bs + n0 * 64 + 16 * qA);
            uint4 b1 = *(const uint4*)(Bs + (n0 + 8) * 64 + 16 * qA);
#pragma unroll
            for (int mf = 0; mf < 4; mf++) mma_fp16(acc[mf][2 * h],     af[mf][0], b0.x, b0.y);
#pragma unroll
            for (int mf = 0; mf < 4; mf++) mma_fp16(acc[mf][2 * h + 1], af[mf][0], b1.x, b1.y);
#pragma unroll
            for (int mf = 0; mf < 4; mf++) mma_fp16(acc[mf][2 * h],     af[mf][1], b0.z, b0.w);
#pragma unroll
            for (int mf = 0; mf < 4; mf++) mma_fp16(acc[mf][2 * h + 1], af[mf][1], b1.z, b1.w);
        }
    };

    // ---- prologue: stage 0 fully staged ----
    loadB(0);
    {
        int4 t[2];
        loadAdjH(0, 0, t); storeAH(0, 0, t);
        loadAdjH(0, 1, t); storeAH(0, 1, t);
    }

#pragma unroll 1
    for (int s = 0; s < NSTG; s++) {
        asm volatile("cp.async.wait_group 0;" ::: "memory");   // B(s) arrived
        __syncthreads();                                       // A(s) stores visible
        const char* base = smem + (s & 1) * BUFSZ;
        if (s + 1 < NSTG) {
            loadB(s + 1);
            int4 r[2];
            loadAdjH(s + 1, 0, r);          // LDG latency hidden by computeKH(0)
            computeKH(base, 0);
            storeAH(s + 1, 0, r);
            loadAdjH(s + 1, 1, r);          // hidden by computeKH(1)
            computeKH(base, 1);
            storeAH(s + 1, 1, r);
        } else {
            computeKH(base, 0);
            computeKH(base, 1);
        }
    }

    // ---- epilogue: split-K partials ----
#pragma unroll
    for (int mf = 0; mf < 4; mf++) {
        int row = row0 + mf * 16 + rA;
#pragma unroll
        for (int nf = 0; nf < 4; nf++) {
            int col = wn * 32 + nf * 8 + qA * 2;
            float* p0 = g_num + ((size_t)ks * NN + row) * DF + col;
            float* p1 = g_num + ((size_t)ks * NN + row + 8) * DF + col;
            *(float2*)p0 = make_float2(acc[mf][nf][0], acc[mf][nf][1]);
            *(float2*)p1 = make_float2(acc[mf][nf][2], acc[mf][nf][3]);
        }
    }
    den += __shfl_xor_sync(0xffffffffu, den, 1);
    den += __shfl_xor_sync(0xffffffffu, den, 2);
    if ((lane & 3) == 0) g_den[(size_t)ks * NN + row0 + ar] = den;
}

// ---------------------------------------------------------------------------
// Combine split-K partials: out = (n0+n1) / (YSCALE*(d0+d1))
// ---------------------------------------------------------------------------
__global__ void k_combine(float* __restrict__ out) {
    int id = blockIdx.x * 256 + threadIdx.x;
    int row = id >> 6, kq = id & 63;
    float4 a = ((const float4*)(g_num + (size_t)row * DF))[kq];
    float4 b = ((const float4*)(g_num + ((size_t)NN + row) * DF))[kq];
    float inv = 1.0f / (YSCALE * (g_den[row] + g_den[NN + row]));
    float4 o;
    o.x = (a.x + b.x) * inv;
    o.y = (a.y + b.y) * inv;
    o.z = (a.z + b.z) * inv;
    o.w = (a.w + b.w) * inv;
    ((float4*)out)[id] = o;
}

// ---------------------------------------------------------------------------
extern "C" void kernel_launch(void* const* d_in, const int* in_sizes, int n_in,
                              void* d_out, int out_size) {
    const float* input = (const float*)d_in[0];
    const int*   adj   = (const int*)d_in[1];
    const float* A     = (const float*)d_in[2];
    float* out = (float*)d_out;

    cudaFuncSetAttribute(k_main, cudaFuncAttributeMaxDynamicSharedMemorySize, SMEM_BYTES);

    k_h2<<<NN / 8, 256>>>(input, A);
    k_u<<<1, 1024>>>();
    k_y<<<dim3(NN / 32, DF / 32), dim3(32, 8)>>>(input);
    k_main<<<256, 256, SMEM_BYTES>>>(adj);
    k_combine<<<(NN * DF / 4) / 256, 256>>>(out);
}